// round 14
// baseline (speedup 1.0000x reference)
#include <cuda_runtime.h>
#include <cuda_bf16.h>
#include <cstdint>

#define NB   4
#define NC   512
#define NS   4096
#define NG   32
#define CPG  16
#define EPSV 1e-6f
#define SCALEV 0.04419417382415922f   // 1/sqrt(512)

// ---------------------------------------------------------------------------
// Scratch (device globals)
// ---------------------------------------------------------------------------
__device__ __nv_bfloat16 g_xnT[(size_t)NB * NS * NC];     // xn^T [b][s][c]
__device__ __nv_bfloat16 g_w3b[3 * NC * NC];              // qkv_w bf16
__device__ __nv_bfloat16 g_wpb[NC * NC];                  // proj_w bf16
__device__ __nv_bfloat16 g_qkT[(size_t)NB * NS * 1024];   // [b][s][ q(512) | k(512) ]
__device__ __nv_bfloat16 g_v [(size_t)NB * NC * NS];      // v   [b][c][j]
__device__ __nv_bfloat16 g_attn[(size_t)NB * NS * NS];    // bf16 e=exp(s) [b][i][j]
__device__ float         g_part[(size_t)NB * NS * 32];    // per-(row, jtile) partial sums
__device__ float         g_rsum[(size_t)NB * NS];         // 1 / rowsum
__device__ __nv_bfloat16 g_hT[(size_t)NB * NS * NC];      // h^T [b][i][c]

__device__ __forceinline__ uint32_t smem_u32(const void* p) {
    uint32_t a;
    asm("{ .reg .u64 t; cvta.to.shared.u64 t, %1; cvt.u32.u64 %0, t; }" : "=r"(a) : "l"(p));
    return a;
}

#define CP_ASYNC16(dst, src) \
    asm volatile("cp.async.cg.shared.global [%0], [%1], 16;" :: "r"(dst), "l"(src))
#define CP_COMMIT() asm volatile("cp.async.commit_group;" ::: "memory")
#define CP_WAIT1()  asm volatile("cp.async.wait_group 1;" ::: "memory")

#define STAGE_BYTES 32768   // A(16KB) + B(16KB)
#define NSTAGES 3           // 96KB dynamic smem -> 2 CTAs/SM

// ---------------------------------------------------------------------------
// bf16 GEMM via mma.sync: D[m][n] = sum_k A[m][k]*B[n][k]
// 128x128 block tile, BK=64, 4 warps (warp tile 64x64, 2x2 grid), 128 threads,
// 3-stage cp.async, 2 CTAs/SM, A-fragment double buffering (sw-pipelined
// across ks steps to hide ldmatrix latency at 2 warps/SMSP).
// epilogue modes:
//   base:       out = D*scale + bias (+resid)
//   expPart!=0: out = exp(D*scale) [bf16], per-row partial sums -> expPart
//   mScale!=0:  out *= mScale[bz*mStride + m]  (per-m multiplier)
// ---------------------------------------------------------------------------
__global__ __launch_bounds__(128, 2) void gemm_bf16_kernel(
    const __nv_bfloat16* __restrict__ A, const __nv_bfloat16* __restrict__ B,
    size_t strideA, size_t strideB, int lda, int ldb, int K,
    float* outF, __nv_bfloat16* outB, size_t strideO, int ldc,
    const float* __restrict__ bias, int biasMode, float scale,
    const float* __restrict__ resid, size_t strideR,
    float* __restrict__ expPart,
    const float* __restrict__ mScale, size_t mStride)
{
    extern __shared__ char smem[];
    const uint32_t sbase = smem_u32(smem);
    const int tid  = threadIdx.x;
    const int wid  = tid >> 5, lane = tid & 31;
    const int wm   = wid & 1;
    const int wnw  = wid >> 1;
    const int m0   = blockIdx.y * 128, n0 = blockIdx.x * 128;
    const int bz   = blockIdx.z;

    const __nv_bfloat16* Ab = A + (size_t)bz * strideA + (size_t)m0 * lda;
    const __nv_bfloat16* Bb = B + (size_t)bz * strideB + (size_t)n0 * ldb;

    float acc[4][8][4];
#pragma unroll
    for (int i = 0; i < 4; i++)
#pragma unroll
        for (int j = 0; j < 8; j++)
#pragma unroll
            for (int r = 0; r < 4; r++) acc[i][j][r] = 0.f;

    const int NKc = K >> 6;

    // per-warp A-fragment swizzled base offsets (ks-dependent part added later)
    uint32_t a_off[4];
#pragma unroll
    for (int i = 0; i < 4; i++) {
        int m = wm * 64 + i * 16 + (lane & 15);
        int kb = (lane >> 4) * 8;
        uint32_t off = (uint32_t)(m * 128 + kb * 2);
        a_off[i] = off;   // swizzle applied after adding ks*32 bytes
    }
    uint32_t b_off[4];
#pragma unroll
    for (int j2 = 0; j2 < 4; j2++) {
        int n = wnw * 64 + j2 * 16 + (lane & 7) + ((lane >> 4) << 3);
        int kb = (((lane >> 3) & 1) << 3);
        b_off[j2] = (uint32_t)(n * 128 + kb * 2);
    }

#pragma unroll
    for (int st = 0; st < 2; st++) {
        if (st < NKc) {
            const uint32_t dst = sbase + st * STAGE_BYTES;
            const __nv_bfloat16* Ak = Ab + (st << 6);
            const __nv_bfloat16* Bk = Bb + (st << 6);
#pragma unroll
            for (int t = 0; t < 8; t++) {
                int idx = tid + t * 128;
                int row = idx >> 3, c16 = idx & 7;
                uint32_t off = (uint32_t)(row * 128 + c16 * 16);
                off ^= ((off >> 3) & 0x70);
                CP_ASYNC16(dst + off,         Ak + (size_t)row * lda + c16 * 8);
                CP_ASYNC16(dst + 16384 + off, Bk + (size_t)row * ldb + c16 * 8);
            }
        }
        CP_COMMIT();
    }

    int bufc = 0;
    for (int kc = 0; kc < NKc; kc++) {
        CP_WAIT1();
        __syncthreads();

        if (kc + 2 < NKc) {
            int bufn = bufc + 2; if (bufn >= NSTAGES) bufn -= NSTAGES;
            const uint32_t dst = sbase + bufn * STAGE_BYTES;
            const __nv_bfloat16* Ak = Ab + ((kc + 2) << 6);
            const __nv_bfloat16* Bk = Bb + ((kc + 2) << 6);
#pragma unroll
            for (int t = 0; t < 8; t++) {
                int idx = tid + t * 128;
                int row = idx >> 3, c16 = idx & 7;
                uint32_t off = (uint32_t)(row * 128 + c16 * 16);
                off ^= ((off >> 3) & 0x70);
                CP_ASYNC16(dst + off,         Ak + (size_t)row * lda + c16 * 8);
                CP_ASYNC16(dst + 16384 + off, Bk + (size_t)row * ldb + c16 * 8);
            }
        }
        CP_COMMIT();

        const uint32_t bufA = sbase + bufc * STAGE_BYTES;
        const uint32_t bufB = bufA + 16384;

        // ---- software-pipelined ks loop: A-frags double buffered ----
        uint32_t afb[2][4][4];
#pragma unroll
        for (int i = 0; i < 4; i++) {
            uint32_t off = a_off[i];                 // ks = 0
            off ^= ((off >> 3) & 0x70);
            asm volatile("ldmatrix.sync.aligned.m8n8.x4.shared.b16 {%0,%1,%2,%3}, [%4];"
                : "=r"(afb[0][i][0]), "=r"(afb[0][i][1]), "=r"(afb[0][i][2]), "=r"(afb[0][i][3])
                : "r"(bufA + off));
        }
#pragma unroll
        for (int ks = 0; ks < 4; ks++) {
            const int cur = ks & 1;
            if (ks < 3) {
#pragma unroll
                for (int i = 0; i < 4; i++) {
                    uint32_t off = a_off[i] + (uint32_t)((ks + 1) * 32);
                    off ^= ((off >> 3) & 0x70);
                    asm volatile("ldmatrix.sync.aligned.m8n8.x4.shared.b16 {%0,%1,%2,%3}, [%4];"
                        : "=r"(afb[cur ^ 1][i][0]), "=r"(afb[cur ^ 1][i][1]),
                          "=r"(afb[cur ^ 1][i][2]), "=r"(afb[cur ^ 1][i][3])
                        : "r"(bufA + off));
                }
            }
#pragma unroll
            for (int j2 = 0; j2 < 4; j2++) {
                uint32_t bf[4];
                uint32_t off = b_off[j2] + (uint32_t)(ks * 32);
                off ^= ((off >> 3) & 0x70);
                asm volatile("ldmatrix.sync.aligned.m8n8.x4.shared.b16 {%0,%1,%2,%3}, [%4];"
                    : "=r"(bf[0]), "=r"(bf[1]), "=r"(bf[2]), "=r"(bf[3])
                    : "r"(bufB + off));
#pragma unroll
                for (int i = 0; i < 4; i++) {
                    asm volatile(
                        "mma.sync.aligned.m16n8k16.row.col.f32.bf16.bf16.f32 "
                        "{%0,%1,%2,%3}, {%4,%5,%6,%7}, {%8,%9}, {%0,%1,%2,%3};"
                        : "+f"(acc[i][2*j2][0]), "+f"(acc[i][2*j2][1]),
                          "+f"(acc[i][2*j2][2]), "+f"(acc[i][2*j2][3])
                        : "r"(afb[cur][i][0]), "r"(afb[cur][i][1]),
                          "r"(afb[cur][i][2]), "r"(afb[cur][i][3]),
                          "r"(bf[0]), "r"(bf[1]));
                    asm volatile(
                        "mma.sync.aligned.m16n8k16.row.col.f32.bf16.bf16.f32 "
                        "{%0,%1,%2,%3}, {%4,%5,%6,%7}, {%8,%9}, {%0,%1,%2,%3};"
                        : "+f"(acc[i][2*j2+1][0]), "+f"(acc[i][2*j2+1][1]),
                          "+f"(acc[i][2*j2+1][2]), "+f"(acc[i][2*j2+1][3])
                        : "r"(afb[cur][i][0]), "r"(afb[cur][i][1]),
                          "r"(afb[cur][i][2]), "r"(afb[cur][i][3]),
                          "r"(bf[2]), "r"(bf[3]));
                }
            }
        }
        __syncthreads();
        if (++bufc == NSTAGES) bufc = 0;
    }

    // ---- epilogue ----
    float* rowtree = (float*)smem;
    const int gq = lane >> 2;
    const int qt = lane & 3;
#pragma unroll
    for (int i = 0; i < 4; i++) {
        const int r0 = m0 + wm * 64 + i * 16 + gq;
        const int r1 = r0 + 8;
        const float bm0 = (biasMode == 1) ? bias[r0] : 0.f;
        const float bm1 = (biasMode == 1) ? bias[r1] : 0.f;
        const float ms0 = mScale ? mScale[(size_t)bz * mStride + r0] : 1.f;
        const float ms1 = mScale ? mScale[(size_t)bz * mStride + r1] : 1.f;
        float sum0 = 0.f, sum1 = 0.f;
#pragma unroll
        for (int j = 0; j < 8; j++) {
            const int n = n0 + wnw * 64 + j * 8 + qt * 2;
            float f00 = acc[i][j][0] * scale + bm0;
            float f01 = acc[i][j][1] * scale + bm0;
            float f10 = acc[i][j][2] * scale + bm1;
            float f11 = acc[i][j][3] * scale + bm1;
            if (biasMode == 2) {
                float b0v = bias[n], b1v = bias[n + 1];
                f00 += b0v; f01 += b1v; f10 += b0v; f11 += b1v;
            }
            if (expPart) {
                f00 = __expf(f00); f01 = __expf(f01);
                f10 = __expf(f10); f11 = __expf(f11);
                sum0 += f00 + f01; sum1 += f10 + f11;
            }
            if (mScale) { f00 *= ms0; f01 *= ms0; f10 *= ms1; f11 *= ms1; }
            if (outB) {
                __nv_bfloat16* op = outB + (size_t)bz * strideO;
                __nv_bfloat162 h0 = __floats2bfloat162_rn(f00, f01);
                __nv_bfloat162 h1 = __floats2bfloat162_rn(f10, f11);
                *(uint32_t*)(op + (size_t)r0 * ldc + n) = *reinterpret_cast<uint32_t*>(&h0);
                *(uint32_t*)(op + (size_t)r1 * ldc + n) = *reinterpret_cast<uint32_t*>(&h1);
            } else {
                float* op = outF + (size_t)bz * strideO;
                if (resid) {
                    const float* rp = resid + (size_t)bz * strideR;
                    float2 v0 = *(const float2*)(rp + (size_t)r0 * ldc + n);
                    float2 v1 = *(const float2*)(rp + (size_t)r1 * ldc + n);
                    f00 += v0.x; f01 += v0.y; f10 += v1.x; f11 += v1.y;
                }
                *(float2*)(op + (size_t)r0 * ldc + n) = make_float2(f00, f01);
                *(float2*)(op + (size_t)r1 * ldc + n) = make_float2(f10, f11);
            }
        }
        if (expPart) {
            rowtree[tid * 8 + i * 2 + 0] = sum0;
            rowtree[tid * 8 + i * 2 + 1] = sum1;
        }
    }
    if (expPart) {
        __syncthreads();
        {
            const int r   = tid;
            const int ii  = (r & 63) >> 4;
            const int sel = (r >> 3) & 1;
            const int g2  = r & 7;
            const int w2  = r >> 6;
            float s = 0.f;
#pragma unroll
            for (int wn2 = 0; wn2 < 2; wn2++)
#pragma unroll
                for (int qt2 = 0; qt2 < 4; qt2++) {
                    int t = (wn2 * 2 + w2) * 32 + g2 * 4 + qt2;
                    s += rowtree[t * 8 + ii * 2 + sel];
                }
            expPart[((size_t)bz * NS + m0 + r) * 32 + blockIdx.x] = s;
        }
    }
}

// ---------------------------------------------------------------------------
__global__ void rowsum_recip_kernel() {
    const int r = blockIdx.x * 256 + threadIdx.x;
    const float4* p = (const float4*)(g_part + (size_t)r * 32);
    float s = 0.f;
#pragma unroll
    for (int t = 0; t < 8; t++) {
        float4 v = p[t];
        s += v.x + v.y + v.z + v.w;
    }
    g_rsum[r] = 1.0f / s;
}

// ---------------------------------------------------------------------------
// GroupNorm -> transposed bf16 output  xnT[b][s][c]  (two-pass, fp32-accurate)
// ---------------------------------------------------------------------------
__global__ __launch_bounds__(512) void groupnorm_kernel(
    const float* __restrict__ x,
    const float* __restrict__ w,
    const float* __restrict__ bvec) {
    const int bg = blockIdx.x;
    const int b = bg / NG, g = bg % NG;
    const int N = CPG * NS;
    const float* xp = x + ((size_t)b * NC + (size_t)g * CPG) * NS;

    float s = 0.f, ss = 0.f;
    for (int i = threadIdx.x; i < N; i += 512) {
        float v = xp[i];
        s += v; ss += v * v;
    }
    __shared__ float sh[512], sh2[512];
    sh[threadIdx.x] = s; sh2[threadIdx.x] = ss;
    __syncthreads();
    for (int o = 256; o > 0; o >>= 1) {
        if (threadIdx.x < o) { sh[threadIdx.x] += sh[threadIdx.x + o]; sh2[threadIdx.x] += sh2[threadIdx.x + o]; }
        __syncthreads();
    }
    const float mean = sh[0] / N;
    const float var  = sh2[0] / N - mean * mean;
    const float rstd = rsqrtf(var + EPSV);

    float wr[CPG], br[CPG];
#pragma unroll
    for (int c = 0; c < CPG; c++) { wr[c] = w[g * CPG + c] * rstd; br[c] = bvec[g * CPG + c] - mean * wr[c]; }

    for (int sp = threadIdx.x; sp < NS; sp += 512) {
        uint32_t pk[8];
#pragma unroll
        for (int c2 = 0; c2 < 8; c2++) {
            float f0 = xp[(size_t)(2 * c2)     * NS + sp] * wr[2 * c2]     + br[2 * c2];
            float f1 = xp[(size_t)(2 * c2 + 1) * NS + sp] * wr[2 * c2 + 1] + br[2 * c2 + 1];
            __nv_bfloat162 h2 = __floats2bfloat162_rn(f0, f1);
            pk[c2] = *reinterpret_cast<uint32_t*>(&h2);
        }
        __nv_bfloat16* op = g_xnT + ((size_t)b * NS + sp) * NC + g * CPG;
        *(uint4*)(op)     = make_uint4(pk[0], pk[1], pk[2], pk[3]);
        *(uint4*)(op + 8) = make_uint4(pk[4], pk[5], pk[6], pk[7]);
    }
}

// ---------------------------------------------------------------------------
// Merged weight conversion: qkv_w -> g_w3b, proj_w -> g_wpb in one launch
// ---------------------------------------------------------------------------
__global__ void convert_weights_kernel(const float* __restrict__ qkv_w,
                                       const float* __restrict__ proj_w) {
    const int n1 = 3 * NC * NC;
    const int n2 = NC * NC;
    int i = blockIdx.x * 256 + threadIdx.x;
    if (i < n1) g_w3b[i] = __float2bfloat16(qkv_w[i]);
    else if (i < n1 + n2) g_wpb[i - n1] = __float2bfloat16(proj_w[i - n1]);
}

// ---------------------------------------------------------------------------
extern "C" void kernel_launch(void* const* d_in, const int* in_sizes, int n_in,
                              void* d_out, int out_size) {
    const float* x      = (const float*)d_in[0];
    const float* norm_w = (const float*)d_in[1];
    const float* norm_b = (const float*)d_in[2];
    const float* qkv_w  = (const float*)d_in[3];
    const float* qkv_b  = (const float*)d_in[4];
    const float* proj_w = (const float*)d_in[5];
    const float* proj_b = (const float*)d_in[6];
    float* out = (float*)d_out;

    cudaFuncSetAttribute(gemm_bf16_kernel, cudaFuncAttributeMaxDynamicSharedMemorySize, NSTAGES * STAGE_BYTES);

    __nv_bfloat16 *w3b, *wpb, *xnT, *qkT, *vv, *attn, *hT;
    float *part, *rsum;
    cudaGetSymbolAddress((void**)&w3b, g_w3b);
    cudaGetSymbolAddress((void**)&wpb, g_wpb);
    cudaGetSymbolAddress((void**)&xnT, g_xnT);
    cudaGetSymbolAddress((void**)&qkT, g_qkT);
    cudaGetSymbolAddress((void**)&vv,  g_v);
    cudaGetSymbolAddress((void**)&attn, g_attn);
    cudaGetSymbolAddress((void**)&hT,  g_hT);
    cudaGetSymbolAddress((void**)&part, g_part);
    cudaGetSymbolAddress((void**)&rsum, g_rsum);

    const size_t SB = (size_t)NS * NC;
    const size_t SQK = (size_t)NS * 1024;
    const size_t SS = (size_t)NS * NS;
    const int SMEM = NSTAGES * STAGE_BYTES;

    convert_weights_kernel<<<(4 * NC * NC + 255) / 256, 256>>>(qkv_w, proj_w);
    groupnorm_kernel<<<NB * NG, 512>>>(x, norm_w, norm_b);

    // fused q+k: qkT[s][0..1023] = xnT . [Wq;Wk]^T  (M=4096, N=1024, K=512)
    gemm_bf16_kernel<<<dim3(8, 32, NB), 128, SMEM>>>(
        xnT, w3b, SB, 0, NC, NC, NC,
        nullptr, qkT, SQK, 1024, qkv_b, 2, 1.0f, nullptr, 0,
        nullptr, nullptr, 0);
    // v[o][s] = Wv . xnT^T    (M=512, N=4096, K=512), bias per-m
    gemm_bf16_kernel<<<dim3(32, 4, NB), 128, SMEM>>>(
        w3b + 2 * (size_t)NC * NC, xnT, 0, SB, NC, NC, NC,
        nullptr, vv, SB, NS, qkv_b + 2 * NC, 1, 1.0f, nullptr, 0,
        nullptr, nullptr, 0);
    // e[i][j] = exp(q . k^T * SCALE), bf16 out + per-row partial sums
    gemm_bf16_kernel<<<dim3(32, 32, NB), 128, SMEM>>>(
        qkT, qkT + 512, SQK, SQK, 1024, 1024, NC,
        nullptr, attn, SS, NS, nullptr, 0, SCALEV, nullptr, 0,
        part, nullptr, 0);
    rowsum_recip_kernel<<<NB * NS / 256, 256>>>();
    // hT[i][c] = (e . v^T) / L_i   (M=4096, N=512, K=4096), bf16 out
    gemm_bf16_kernel<<<dim3(4, 32, NB), 128, SMEM>>>(
        attn, vv, SS, SB, NS, NS, NS,
        nullptr, hT, SB, NC, nullptr, 0, 1.0f, nullptr, 0,
        nullptr, rsum, NS);
    // out[o][s] = Wp . hT^T + x + pb   (M=512, N=4096, K=512), fp32 + resid
    gemm_bf16_kernel<<<dim3(32, 4, NB), 128, SMEM>>>(
        wpb, hT, 0, SB, NC, NC, NC,
        out, nullptr, (size_t)NC * NS, NS, proj_b, 1, 1.0f, x, (size_t)NC * NS,
        nullptr, nullptr, 0);
}

// round 15
// speedup vs baseline: 1.0328x; 1.0328x over previous
#include <cuda_runtime.h>
#include <cuda_bf16.h>
#include <cstdint>

#define NB   4
#define NC   512
#define NS   4096
#define NG   32
#define CPG  16
#define EPSV 1e-6f
#define SCALEV 0.04419417382415922f   // 1/sqrt(512)

// ---------------------------------------------------------------------------
// Scratch (device globals)
// ---------------------------------------------------------------------------
__device__ __nv_bfloat16 g_xnT[(size_t)NB * NS * NC];     // xn^T [b][s][c]
__device__ __nv_bfloat16 g_w3b[3 * NC * NC];              // qkv_w bf16
__device__ __nv_bfloat16 g_wpb[NC * NC];                  // proj_w bf16
__device__ __nv_bfloat16 g_qkT[(size_t)NB * NS * 1024];   // [b][s][ q(512) | k(512) ]
__device__ __nv_bfloat16 g_v [(size_t)NB * NC * NS];      // v   [b][c][j]
__device__ __nv_bfloat16 g_attn[(size_t)NB * NS * NS];    // bf16 e=exp(s) [b][i][j]
__device__ float         g_part[(size_t)NB * NS * 32];    // per-(row, jtile) partial sums
__device__ float         g_rsum[(size_t)NB * NS];         // 1 / rowsum
__device__ __nv_bfloat16 g_hT[(size_t)NB * NS * NC];      // h^T [b][i][c]

__device__ __forceinline__ uint32_t smem_u32(const void* p) {
    uint32_t a;
    asm("{ .reg .u64 t; cvta.to.shared.u64 t, %1; cvt.u32.u64 %0, t; }" : "=r"(a) : "l"(p));
    return a;
}

#define CP_ASYNC16(dst, src) \
    asm volatile("cp.async.cg.shared.global [%0], [%1], 16;" :: "r"(dst), "l"(src))
#define CP_COMMIT() asm volatile("cp.async.commit_group;" ::: "memory")
#define CP_WAIT1()  asm volatile("cp.async.wait_group 1;" ::: "memory")

#define STAGE_BYTES 32768   // A(16KB) + B(16KB)
#define NSTAGES 3           // 96KB dynamic smem -> 2 CTAs/SM

// ---------------------------------------------------------------------------
// bf16 GEMM via mma.sync: D[m][n] = sum_k A[m][k]*B[n][k]
// 128x128 block tile, BK=64, 4 warps (warp tile 64x64, 2x2 grid), 128 threads,
// 3-stage cp.async, 2 CTAs/SM.  (R10-measured-best; do not touch.)
// epilogue modes:
//   base:       out = D*scale + bias (+resid)
//   expPart!=0: out = exp(D*scale) [bf16], per-row partial sums -> expPart
//   mScale!=0:  out *= mScale[bz*mStride + m]  (per-m multiplier)
// ---------------------------------------------------------------------------
__global__ __launch_bounds__(128, 2) void gemm_bf16_kernel(
    const __nv_bfloat16* __restrict__ A, const __nv_bfloat16* __restrict__ B,
    size_t strideA, size_t strideB, int lda, int ldb, int K,
    float* outF, __nv_bfloat16* outB, size_t strideO, int ldc,
    const float* __restrict__ bias, int biasMode, float scale,
    const float* __restrict__ resid, size_t strideR,
    float* __restrict__ expPart,
    const float* __restrict__ mScale, size_t mStride)
{
    extern __shared__ char smem[];
    const uint32_t sbase = smem_u32(smem);
    const int tid  = threadIdx.x;
    const int wid  = tid >> 5, lane = tid & 31;
    const int wm   = wid & 1;
    const int wnw  = wid >> 1;
    const int m0   = blockIdx.y * 128, n0 = blockIdx.x * 128;
    const int bz   = blockIdx.z;

    const __nv_bfloat16* Ab = A + (size_t)bz * strideA + (size_t)m0 * lda;
    const __nv_bfloat16* Bb = B + (size_t)bz * strideB + (size_t)n0 * ldb;

    float acc[4][8][4];
#pragma unroll
    for (int i = 0; i < 4; i++)
#pragma unroll
        for (int j = 0; j < 8; j++)
#pragma unroll
            for (int r = 0; r < 4; r++) acc[i][j][r] = 0.f;

    const int NKc = K >> 6;

#pragma unroll
    for (int st = 0; st < 2; st++) {
        if (st < NKc) {
            const uint32_t dst = sbase + st * STAGE_BYTES;
            const __nv_bfloat16* Ak = Ab + (st << 6);
            const __nv_bfloat16* Bk = Bb + (st << 6);
#pragma unroll
            for (int t = 0; t < 8; t++) {
                int idx = tid + t * 128;
                int row = idx >> 3, c16 = idx & 7;
                uint32_t off = (uint32_t)(row * 128 + c16 * 16);
                off ^= ((off >> 3) & 0x70);
                CP_ASYNC16(dst + off,         Ak + (size_t)row * lda + c16 * 8);
                CP_ASYNC16(dst + 16384 + off, Bk + (size_t)row * ldb + c16 * 8);
            }
        }
        CP_COMMIT();
    }

    int bufc = 0;
    for (int kc = 0; kc < NKc; kc++) {
        CP_WAIT1();
        __syncthreads();

        if (kc + 2 < NKc) {
            int bufn = bufc + 2; if (bufn >= NSTAGES) bufn -= NSTAGES;
            const uint32_t dst = sbase + bufn * STAGE_BYTES;
            const __nv_bfloat16* Ak = Ab + ((kc + 2) << 6);
            const __nv_bfloat16* Bk = Bb + ((kc + 2) << 6);
#pragma unroll
            for (int t = 0; t < 8; t++) {
                int idx = tid + t * 128;
                int row = idx >> 3, c16 = idx & 7;
                uint32_t off = (uint32_t)(row * 128 + c16 * 16);
                off ^= ((off >> 3) & 0x70);
                CP_ASYNC16(dst + off,         Ak + (size_t)row * lda + c16 * 8);
                CP_ASYNC16(dst + 16384 + off, Bk + (size_t)row * ldb + c16 * 8);
            }
        }
        CP_COMMIT();

        const uint32_t bufA = sbase + bufc * STAGE_BYTES;
        const uint32_t bufB = bufA + 16384;

#pragma unroll
        for (int ks = 0; ks < 4; ks++) {
            uint32_t af[4][4];
#pragma unroll
            for (int i = 0; i < 4; i++) {
                int m = wm * 64 + i * 16 + (lane & 15);
                int k = ks * 16 + (lane >> 4) * 8;
                uint32_t off = (uint32_t)(m * 128 + k * 2);
                off ^= ((off >> 3) & 0x70);
                asm volatile("ldmatrix.sync.aligned.m8n8.x4.shared.b16 {%0,%1,%2,%3}, [%4];"
                    : "=r"(af[i][0]), "=r"(af[i][1]), "=r"(af[i][2]), "=r"(af[i][3])
                    : "r"(bufA + off));
            }
#pragma unroll
            for (int j2 = 0; j2 < 4; j2++) {
                uint32_t bf[4];
                int n = wnw * 64 + j2 * 16 + (lane & 7) + ((lane >> 4) << 3);
                int k = ks * 16 + (((lane >> 3) & 1) << 3);
                uint32_t off = (uint32_t)(n * 128 + k * 2);
                off ^= ((off >> 3) & 0x70);
                asm volatile("ldmatrix.sync.aligned.m8n8.x4.shared.b16 {%0,%1,%2,%3}, [%4];"
                    : "=r"(bf[0]), "=r"(bf[1]), "=r"(bf[2]), "=r"(bf[3])
                    : "r"(bufB + off));
#pragma unroll
                for (int i = 0; i < 4; i++) {
                    asm volatile(
                        "mma.sync.aligned.m16n8k16.row.col.f32.bf16.bf16.f32 "
                        "{%0,%1,%2,%3}, {%4,%5,%6,%7}, {%8,%9}, {%0,%1,%2,%3};"
                        : "+f"(acc[i][2*j2][0]), "+f"(acc[i][2*j2][1]),
                          "+f"(acc[i][2*j2][2]), "+f"(acc[i][2*j2][3])
                        : "r"(af[i][0]), "r"(af[i][1]), "r"(af[i][2]), "r"(af[i][3]),
                          "r"(bf[0]), "r"(bf[1]));
                    asm volatile(
                        "mma.sync.aligned.m16n8k16.row.col.f32.bf16.bf16.f32 "
                        "{%0,%1,%2,%3}, {%4,%5,%6,%7}, {%8,%9}, {%0,%1,%2,%3};"
                        : "+f"(acc[i][2*j2+1][0]), "+f"(acc[i][2*j2+1][1]),
                          "+f"(acc[i][2*j2+1][2]), "+f"(acc[i][2*j2+1][3])
                        : "r"(af[i][0]), "r"(af[i][1]), "r"(af[i][2]), "r"(af[i][3]),
                          "r"(bf[2]), "r"(bf[3]));
                }
            }
        }
        __syncthreads();
        if (++bufc == NSTAGES) bufc = 0;
    }

    // ---- epilogue ----
    float* rowtree = (float*)smem;
    const int gq = lane >> 2;
    const int qt = lane & 3;
#pragma unroll
    for (int i = 0; i < 4; i++) {
        const int r0 = m0 + wm * 64 + i * 16 + gq;
        const int r1 = r0 + 8;
        const float bm0 = (biasMode == 1) ? bias[r0] : 0.f;
        const float bm1 = (biasMode == 1) ? bias[r1] : 0.f;
        const float ms0 = mScale ? mScale[(size_t)bz * mStride + r0] : 1.f;
        const float ms1 = mScale ? mScale[(size_t)bz * mStride + r1] : 1.f;
        float sum0 = 0.f, sum1 = 0.f;
#pragma unroll
        for (int j = 0; j < 8; j++) {
            const int n = n0 + wnw * 64 + j * 8 + qt * 2;
            float f00 = acc[i][j][0] * scale + bm0;
            float f01 = acc[i][j][1] * scale + bm0;
            float f10 = acc[i][j][2] * scale + bm1;
            float f11 = acc[i][j][3] * scale + bm1;
            if (biasMode == 2) {
                float b0v = bias[n], b1v = bias[n + 1];
                f00 += b0v; f01 += b1v; f10 += b0v; f11 += b1v;
            }
            if (expPart) {
                f00 = __expf(f00); f01 = __expf(f01);
                f10 = __expf(f10); f11 = __expf(f11);
                sum0 += f00 + f01; sum1 += f10 + f11;
            }
            if (mScale) { f00 *= ms0; f01 *= ms0; f10 *= ms1; f11 *= ms1; }
            if (outB) {
                __nv_bfloat16* op = outB + (size_t)bz * strideO;
                __nv_bfloat162 h0 = __floats2bfloat162_rn(f00, f01);
                __nv_bfloat162 h1 = __floats2bfloat162_rn(f10, f11);
                *(uint32_t*)(op + (size_t)r0 * ldc + n) = *reinterpret_cast<uint32_t*>(&h0);
                *(uint32_t*)(op + (size_t)r1 * ldc + n) = *reinterpret_cast<uint32_t*>(&h1);
            } else {
                float* op = outF + (size_t)bz * strideO;
                if (resid) {
                    const float* rp = resid + (size_t)bz * strideR;
                    float2 v0 = *(const float2*)(rp + (size_t)r0 * ldc + n);
                    float2 v1 = *(const float2*)(rp + (size_t)r1 * ldc + n);
                    f00 += v0.x; f01 += v0.y; f10 += v1.x; f11 += v1.y;
                }
                *(float2*)(op + (size_t)r0 * ldc + n) = make_float2(f00, f01);
                *(float2*)(op + (size_t)r1 * ldc + n) = make_float2(f10, f11);
            }
        }
        if (expPart) {
            rowtree[tid * 8 + i * 2 + 0] = sum0;
            rowtree[tid * 8 + i * 2 + 1] = sum1;
        }
    }
    if (expPart) {
        __syncthreads();
        {
            const int r   = tid;
            const int ii  = (r & 63) >> 4;
            const int sel = (r >> 3) & 1;
            const int g2  = r & 7;
            const int w2  = r >> 6;
            float s = 0.f;
#pragma unroll
            for (int wn2 = 0; wn2 < 2; wn2++)
#pragma unroll
                for (int qt2 = 0; qt2 < 4; qt2++) {
                    int t = (wn2 * 2 + w2) * 32 + g2 * 4 + qt2;
                    s += rowtree[t * 8 + ii * 2 + sel];
                }
            expPart[((size_t)bz * NS + m0 + r) * 32 + blockIdx.x] = s;
        }
    }
}

// ---------------------------------------------------------------------------
__global__ void rowsum_recip_kernel() {
    const int r = blockIdx.x * 256 + threadIdx.x;
    const float4* p = (const float4*)(g_part + (size_t)r * 32);
    float s = 0.f;
#pragma unroll
    for (int t = 0; t < 8; t++) {
        float4 v = p[t];
        s += v.x + v.y + v.z + v.w;
    }
    g_rsum[r] = 1.0f / s;
}

// ---------------------------------------------------------------------------
// GroupNorm -> transposed bf16 output  xnT[b][s][c]  (two-pass, fp32-accurate)
// ---------------------------------------------------------------------------
__global__ __launch_bounds__(512) void groupnorm_kernel(
    const float* __restrict__ x,
    const float* __restrict__ w,
    const float* __restrict__ bvec) {
    const int bg = blockIdx.x;
    const int b = bg / NG, g = bg % NG;
    const int N = CPG * NS;
    const float* xp = x + ((size_t)b * NC + (size_t)g * CPG) * NS;

    float s = 0.f, ss = 0.f;
    for (int i = threadIdx.x; i < N; i += 512) {
        float v = xp[i];
        s += v; ss += v * v;
    }
    __shared__ float sh[512], sh2[512];
    sh[threadIdx.x] = s; sh2[threadIdx.x] = ss;
    __syncthreads();
    for (int o = 256; o > 0; o >>= 1) {
        if (threadIdx.x < o) { sh[threadIdx.x] += sh[threadIdx.x + o]; sh2[threadIdx.x] += sh2[threadIdx.x + o]; }
        __syncthreads();
    }
    const float mean = sh[0] / N;
    const float var  = sh2[0] / N - mean * mean;
    const float rstd = rsqrtf(var + EPSV);

    float wr[CPG], br[CPG];
#pragma unroll
    for (int c = 0; c < CPG; c++) { wr[c] = w[g * CPG + c] * rstd; br[c] = bvec[g * CPG + c] - mean * wr[c]; }

    for (int sp = threadIdx.x; sp < NS; sp += 512) {
        uint32_t pk[8];
#pragma unroll
        for (int c2 = 0; c2 < 8; c2++) {
            float f0 = xp[(size_t)(2 * c2)     * NS + sp] * wr[2 * c2]     + br[2 * c2];
            float f1 = xp[(size_t)(2 * c2 + 1) * NS + sp] * wr[2 * c2 + 1] + br[2 * c2 + 1];
            __nv_bfloat162 h2 = __floats2bfloat162_rn(f0, f1);
            pk[c2] = *reinterpret_cast<uint32_t*>(&h2);
        }
        __nv_bfloat16* op = g_xnT + ((size_t)b * NS + sp) * NC + g * CPG;
        *(uint4*)(op)     = make_uint4(pk[0], pk[1], pk[2], pk[3]);
        *(uint4*)(op + 8) = make_uint4(pk[4], pk[5], pk[6], pk[7]);
    }
}

// ---------------------------------------------------------------------------
// Merged weight conversion: qkv_w -> g_w3b, proj_w -> g_wpb in one launch
// ---------------------------------------------------------------------------
__global__ void convert_weights_kernel(const float* __restrict__ qkv_w,
                                       const float* __restrict__ proj_w) {
    const int n1 = 3 * NC * NC;
    const int n2 = NC * NC;
    int i = blockIdx.x * 256 + threadIdx.x;
    if (i < n1) g_w3b[i] = __float2bfloat16(qkv_w[i]);
    else if (i < n1 + n2) g_wpb[i - n1] = __float2bfloat16(proj_w[i - n1]);
}

// ---------------------------------------------------------------------------
extern "C" void kernel_launch(void* const* d_in, const int* in_sizes, int n_in,
                              void* d_out, int out_size) {
    const float* x      = (const float*)d_in[0];
    const float* norm_w = (const float*)d_in[1];
    const float* norm_b = (const float*)d_in[2];
    const float* qkv_w  = (const float*)d_in[3];
    const float* qkv_b  = (const float*)d_in[4];
    const float* proj_w = (const float*)d_in[5];
    const float* proj_b = (const float*)d_in[6];
    float* out = (float*)d_out;

    cudaFuncSetAttribute(gemm_bf16_kernel, cudaFuncAttributeMaxDynamicSharedMemorySize, NSTAGES * STAGE_BYTES);

    __nv_bfloat16 *w3b, *wpb, *xnT, *qkT, *vv, *attn, *hT;
    float *part, *rsum;
    cudaGetSymbolAddress((void**)&w3b, g_w3b);
    cudaGetSymbolAddress((void**)&wpb, g_wpb);
    cudaGetSymbolAddress((void**)&xnT, g_xnT);
    cudaGetSymbolAddress((void**)&qkT, g_qkT);
    cudaGetSymbolAddress((void**)&vv,  g_v);
    cudaGetSymbolAddress((void**)&attn, g_attn);
    cudaGetSymbolAddress((void**)&hT,  g_hT);
    cudaGetSymbolAddress((void**)&part, g_part);
    cudaGetSymbolAddress((void**)&rsum, g_rsum);

    const size_t SB = (size_t)NS * NC;
    const size_t SQK = (size_t)NS * 1024;
    const size_t SS = (size_t)NS * NS;
    const int SMEM = NSTAGES * STAGE_BYTES;

    convert_weights_kernel<<<(4 * NC * NC + 255) / 256, 256>>>(qkv_w, proj_w);
    groupnorm_kernel<<<NB * NG, 512>>>(x, norm_w, norm_b);

    // fused q+k: qkT[s][0..1023] = xnT . [Wq;Wk]^T  (M=4096, N=1024, K=512)
    gemm_bf16_kernel<<<dim3(8, 32, NB), 128, SMEM>>>(
        xnT, w3b, SB, 0, NC, NC, NC,
        nullptr, qkT, SQK, 1024, qkv_b, 2, 1.0f, nullptr, 0,
        nullptr, nullptr, 0);
    // v[o][s] = Wv . xnT^T    (M=512, N=4096, K=512), bias per-m
    gemm_bf16_kernel<<<dim3(32, 4, NB), 128, SMEM>>>(
        w3b + 2 * (size_t)NC * NC, xnT, 0, SB, NC, NC, NC,
        nullptr, vv, SB, NS, qkv_b + 2 * NC, 1, 1.0f, nullptr, 0,
        nullptr, nullptr, 0);
    // e[i][j] = exp(q . k^T * SCALE), bf16 out + per-row partial sums
    gemm_bf16_kernel<<<dim3(32, 32, NB), 128, SMEM>>>(
        qkT, qkT + 512, SQK, SQK, 1024, 1024, NC,
        nullptr, attn, SS, NS, nullptr, 0, SCALEV, nullptr, 0,
        part, nullptr, 0);
    rowsum_recip_kernel<<<NB * NS / 256, 256>>>();
    // hT[i][c] = (e . v^T) / L_i   (M=4096, N=512, K=4096), bf16 out
    gemm_bf16_kernel<<<dim3(4, 32, NB), 128, SMEM>>>(
        attn, vv, SS, SB, NS, NS, NS,
        nullptr, hT, SB, NC, nullptr, 0, 1.0f, nullptr, 0,
        nullptr, rsum, NS);
    // out[o][s] = Wp . hT^T + x + pb   (M=512, N=4096, K=512), fp32 + resid
    gemm_bf16_kernel<<<dim3(32, 4, NB), 128, SMEM>>>(
        wpb, hT, 0, SB, NC, NC, NC,
        out, nullptr, (size_t)NC * NS, NS, proj_b, 1, 1.0f, x, (size_t)NC * NS,
        nullptr, nullptr, 0);
}